// round 7
// baseline (speedup 1.0000x reference)
#include <cuda_runtime.h>

#define BN  16384   // number of segments
#define TPB 256
#define IT  8       // int4-chunks per lane per warp tile (warp tile = 32*IT*4 = 1024 elems)

// Segment start offsets. g_start[s] = first node index of segment s; g_start[BN] = n.
// Fully rewritten on every launch (no reset pass needed). No cudaMalloc.
__device__ int g_start[BN + 1];

__device__ __forceinline__ void fill_range(int u, int v, int i) {
    // batch is sorted: for every s in (u, v], segment s starts at node i.
    int s  = (u + 1 > 0)  ? u + 1 : 0;
    int se = (v < BN)     ? v     : BN;
    for (; s <= se; ++s) g_start[s] = i;
}

// ---------------- phase A: boundary detection over batch (20 MB) ----------------
__global__ void __launch_bounds__(TPB) boundaries_kernel(
    const int4* __restrict__ bat4,
    const int*  __restrict__ batch,
    int n)
{
    const int lane = threadIdx.x & 31;
    const int warp = blockIdx.x * (TPB / 32) + (threadIdx.x >> 5);
    const int nchunks = n >> 2;           // full int4 chunks
    const int c0 = warp * (32 * IT);

    if (c0 < nchunks) {
        int carry = (c0 == 0) ? -1 : batch[c0 * 4 - 1];  // element before this warp tile
        #pragma unroll
        for (int it = 0; it < IT; ++it) {
            int  c   = c0 + it * 32 + lane;
            bool act = (c < nchunks);
            int4 b   = make_int4(0, 0, 0, 0);
            if (act) b = bat4[c];

            int pl   = __shfl_up_sync(0xffffffffu, b.w, 1);
            int prev = (lane == 0) ? carry : pl;

            if (act) {
                if ((prev ^ b.x) | (b.x ^ b.y) | (b.y ^ b.z) | (b.z ^ b.w)) {
                    int i = c * 4;
                    fill_range(prev, b.x, i);
                    fill_range(b.x,  b.y, i + 1);
                    fill_range(b.y,  b.z, i + 2);
                    fill_range(b.z,  b.w, i + 3);
                }
            }
            carry = __shfl_sync(0xffffffffu, b.w, 31);
        }
    }

    // One thread handles the scalar tail (< 4 elems) and the end sentinel.
    if (blockIdx.x == 0 && threadIdx.x == 0) {
        int i0   = nchunks * 4;
        int prev = (i0 == 0) ? -1 : batch[i0 - 1];
        for (int i = i0; i < n; ++i) {
            int b = batch[i];
            fill_range(prev, b, i);
            prev = b;
        }
        fill_range(prev, BN, n);   // g_start[s]=n beyond the last segment, incl. sentinel
    }
}

// -------- phase B: per-segment contiguous sum + fused MLP (reads x, 80 MB) --------
__global__ void __launch_bounds__(TPB) segmean_mlp_kernel(
    const float4* __restrict__ x,
    const float*  __restrict__ u,
    const float*  __restrict__ W1,  // [5,5] row-major
    const float*  __restrict__ b1,  // [5]
    const float*  __restrict__ W2,  // [5,1]
    const float*  __restrict__ b2,  // [1]
    float* __restrict__ out)
{
    const int seg  = blockIdx.x * (TPB / 32) + (threadIdx.x >> 5);
    if (seg >= BN) return;
    const int lane = threadIdx.x & 31;

    const int s = g_start[seg];
    const int e = g_start[seg + 1];

    float4 a0 = make_float4(0.f, 0.f, 0.f, 0.f);
    float4 a1 = make_float4(0.f, 0.f, 0.f, 0.f);
    float4 a2 = make_float4(0.f, 0.f, 0.f, 0.f);
    float4 a3 = make_float4(0.f, 0.f, 0.f, 0.f);

    int i = s + lane;
    // unrolled-by-4 streaming: 4 independent loads in flight, 4 accumulators
    for (; i + 96 < e; i += 128) {
        float4 v0 = __ldcs(&x[i]);
        float4 v1 = __ldcs(&x[i + 32]);
        float4 v2 = __ldcs(&x[i + 64]);
        float4 v3 = __ldcs(&x[i + 96]);
        a0.x += v0.x; a0.y += v0.y; a0.z += v0.z; a0.w += v0.w;
        a1.x += v1.x; a1.y += v1.y; a1.z += v1.z; a1.w += v1.w;
        a2.x += v2.x; a2.y += v2.y; a2.z += v2.z; a2.w += v2.w;
        a3.x += v3.x; a3.y += v3.y; a3.z += v3.z; a3.w += v3.w;
    }
    // cleanup (0..3 masked warp-strides)
    for (; i < e; i += 32) {
        float4 v0 = __ldcs(&x[i]);
        a0.x += v0.x; a0.y += v0.y; a0.z += v0.z; a0.w += v0.w;
    }
    // pairwise collapse (two independent chains)
    a0.x += a1.x; a0.y += a1.y; a0.z += a1.z; a0.w += a1.w;
    a2.x += a3.x; a2.y += a3.y; a2.z += a3.z; a2.w += a3.w;
    a0.x += a2.x; a0.y += a2.y; a0.z += a2.z; a0.w += a2.w;

    // warp reduction (deterministic tree; 4 independent chains overlap)
    #pragma unroll
    for (int o = 16; o > 0; o >>= 1) {
        a0.x += __shfl_down_sync(0xffffffffu, a0.x, o);
        a0.y += __shfl_down_sync(0xffffffffu, a0.y, o);
        a0.z += __shfl_down_sync(0xffffffffu, a0.z, o);
        a0.w += __shfl_down_sync(0xffffffffu, a0.w, o);
    }

    if (lane == 0) {
        float cnt = (float)(e - s);
        float inv = (cnt > 0.f) ? (1.f / cnt) : 0.f;

        float h[5];
        h[0] = __ldg(&u[seg]);
        h[1] = a0.x * inv; h[2] = a0.y * inv;
        h[3] = a0.z * inv; h[4] = a0.w * inv;

        float o = __ldg(&b2[0]);
        #pragma unroll
        for (int j = 0; j < 5; ++j) {
            float t = __ldg(&b1[j]);
            #pragma unroll
            for (int k = 0; k < 5; ++k) t += h[k] * __ldg(&W1[k * 5 + j]);
            t = (t > 0.f) ? t : 0.1f * t;
            o += t * __ldg(&W2[j]);
        }
        out[seg] = o;
    }
}

extern "C" void kernel_launch(void* const* d_in, const int* in_sizes, int n_in,
                              void* d_out, int out_size) {
    const float* x     = (const float*)d_in[0];
    const int*   batch = (const int*)d_in[1];
    const float* u     = (const float*)d_in[2];
    const float* W1    = (const float*)d_in[3];
    const float* b1    = (const float*)d_in[4];
    const float* W2    = (const float*)d_in[5];
    const float* b2    = (const float*)d_in[6];
    float* out = (float*)d_out;

    int n = in_sizes[1];  // number of nodes

    // phase A: boundary detection
    {
        int nchunks = n >> 2;
        long long nwarps = ((long long)nchunks + (32 * IT) - 1) / (32 * IT);
        int nblocks = (int)((nwarps + (TPB / 32) - 1) / (TPB / 32));
        if (nblocks < 1) nblocks = 1;
        boundaries_kernel<<<nblocks, TPB>>>((const int4*)batch, batch, n);
    }

    // phase B: one warp per segment, sum + MLP fused
    {
        int nblocks = BN / (TPB / 32);   // 2048
        segmean_mlp_kernel<<<nblocks, TPB>>>((const float4*)x, u, W1, b1, W2, b2, out);
    }
}

// round 8
// speedup vs baseline: 1.2637x; 1.2637x over previous
#include <cuda_runtime.h>

#define BN  16384   // number of segments
#define TPB 256
#define IT  8       // int4-chunks per lane per warp tile (warp tile = 32*IT*4 = 1024 elems)

// Segment start offsets. g_start[s] = first node index of segment s; g_start[BN] = n.
// Fully rewritten on every launch (no reset pass needed). No cudaMalloc.
__device__ int g_start[BN + 1];

__device__ __forceinline__ void fill_range(int u, int v, int i) {
    // batch is sorted: for every s in (u, v], segment s starts at node i.
    int s  = (u + 1 > 0)  ? u + 1 : 0;
    int se = (v < BN)     ? v     : BN;
    for (; s <= se; ++s) g_start[s] = i;
}

// ---------------- phase A: boundary detection over batch (20 MB) ----------------
__global__ void __launch_bounds__(TPB) boundaries_kernel(
    const int4* __restrict__ bat4,
    const int*  __restrict__ batch,
    int n)
{
    const int lane = threadIdx.x & 31;
    const int warp = blockIdx.x * (TPB / 32) + (threadIdx.x >> 5);
    const int nchunks = n >> 2;           // full int4 chunks
    const int c0 = warp * (32 * IT);

    if (c0 < nchunks) {
        int carry = (c0 == 0) ? -1 : batch[c0 * 4 - 1];  // element before this warp tile
        #pragma unroll
        for (int it = 0; it < IT; ++it) {
            int  c   = c0 + it * 32 + lane;
            bool act = (c < nchunks);
            int4 b   = make_int4(0, 0, 0, 0);
            if (act) b = bat4[c];

            int pl   = __shfl_up_sync(0xffffffffu, b.w, 1);
            int prev = (lane == 0) ? carry : pl;

            if (act) {
                if ((prev ^ b.x) | (b.x ^ b.y) | (b.y ^ b.z) | (b.z ^ b.w)) {
                    int i = c * 4;
                    fill_range(prev, b.x, i);
                    fill_range(b.x,  b.y, i + 1);
                    fill_range(b.y,  b.z, i + 2);
                    fill_range(b.z,  b.w, i + 3);
                }
            }
            carry = __shfl_sync(0xffffffffu, b.w, 31);
        }
    }

    // One thread handles the scalar tail (< 4 elems) and the end sentinel.
    if (blockIdx.x == 0 && threadIdx.x == 0) {
        int i0   = nchunks * 4;
        int prev = (i0 == 0) ? -1 : batch[i0 - 1];
        for (int i = i0; i < n; ++i) {
            int b = batch[i];
            fill_range(prev, b, i);
            prev = b;
        }
        fill_range(prev, BN, n);   // g_start[s]=n beyond the last segment, incl. sentinel
    }
}

// -------- phase B: per-segment contiguous sum + fused MLP (reads x, 80 MB) --------
__global__ void __launch_bounds__(TPB) segmean_mlp_kernel(
    const float4* __restrict__ x,
    const float*  __restrict__ u,
    const float*  __restrict__ W1,  // [5,5] row-major
    const float*  __restrict__ b1,  // [5]
    const float*  __restrict__ W2,  // [5,1]
    const float*  __restrict__ b2,  // [1]
    float* __restrict__ out)
{
    __shared__ float sW1[25], sb1[5], sW2[5], sb2;
    {
        int t = threadIdx.x;
        if (t < 25)      sW1[t]      = W1[t];
        else if (t < 30) sb1[t - 25] = b1[t - 25];
        else if (t < 35) sW2[t - 30] = W2[t - 30];
        else if (t == 35) sb2        = b2[0];
    }
    __syncthreads();

    const int seg  = blockIdx.x * (TPB / 32) + (threadIdx.x >> 5);  // grid covers BN exactly
    const int lane = threadIdx.x & 31;

    const int s = g_start[seg];
    const int e = g_start[seg + 1];

    float4 a0 = make_float4(0.f, 0.f, 0.f, 0.f);
    float4 a1 = make_float4(0.f, 0.f, 0.f, 0.f);

    int i = s + lane;
    if (i < e) {
        // software-pipelined streaming: next iteration's loads issue before
        // this iteration's accumulates wait on their data.
        float4 v0 = __ldcs(&x[i]);
        float4 v1 = (i + 32 < e) ? __ldcs(&x[i + 32])
                                 : make_float4(0.f, 0.f, 0.f, 0.f);
        for (; i + 96 < e; i += 64) {
            float4 n0 = __ldcs(&x[i + 64]);
            float4 n1 = __ldcs(&x[i + 96]);
            a0.x += v0.x; a0.y += v0.y; a0.z += v0.z; a0.w += v0.w;
            a1.x += v1.x; a1.y += v1.y; a1.z += v1.z; a1.w += v1.w;
            v0 = n0; v1 = n1;
        }
        a0.x += v0.x; a0.y += v0.y; a0.z += v0.z; a0.w += v0.w;
        a1.x += v1.x; a1.y += v1.y; a1.z += v1.z; a1.w += v1.w;
        i += 64;
        if (i < e) {   // at most one masked warp-stride remains
            float4 v = __ldcs(&x[i]);
            a0.x += v.x; a0.y += v.y; a0.z += v.z; a0.w += v.w;
        }
    }
    a0.x += a1.x; a0.y += a1.y; a0.z += a1.z; a0.w += a1.w;

    // warp reduction (deterministic tree; 4 independent chains overlap)
    #pragma unroll
    for (int o = 16; o > 0; o >>= 1) {
        a0.x += __shfl_down_sync(0xffffffffu, a0.x, o);
        a0.y += __shfl_down_sync(0xffffffffu, a0.y, o);
        a0.z += __shfl_down_sync(0xffffffffu, a0.z, o);
        a0.w += __shfl_down_sync(0xffffffffu, a0.w, o);
    }

    if (lane == 0) {
        float cnt = (float)(e - s);
        float inv = (cnt > 0.f) ? (1.f / cnt) : 0.f;

        float h[5];
        h[0] = __ldg(&u[seg]);
        h[1] = a0.x * inv; h[2] = a0.y * inv;
        h[3] = a0.z * inv; h[4] = a0.w * inv;

        float o = sb2;
        #pragma unroll
        for (int j = 0; j < 5; ++j) {
            float t = sb1[j];
            #pragma unroll
            for (int k = 0; k < 5; ++k) t += h[k] * sW1[k * 5 + j];
            t = (t > 0.f) ? t : 0.1f * t;
            o += t * sW2[j];
        }
        out[seg] = o;
    }
}

extern "C" void kernel_launch(void* const* d_in, const int* in_sizes, int n_in,
                              void* d_out, int out_size) {
    const float* x     = (const float*)d_in[0];
    const int*   batch = (const int*)d_in[1];
    const float* u     = (const float*)d_in[2];
    const float* W1    = (const float*)d_in[3];
    const float* b1    = (const float*)d_in[4];
    const float* W2    = (const float*)d_in[5];
    const float* b2    = (const float*)d_in[6];
    float* out = (float*)d_out;

    int n = in_sizes[1];  // number of nodes

    // phase A: boundary detection
    {
        int nchunks = n >> 2;
        long long nwarps = ((long long)nchunks + (32 * IT) - 1) / (32 * IT);
        int nblocks = (int)((nwarps + (TPB / 32) - 1) / (TPB / 32));
        if (nblocks < 1) nblocks = 1;
        boundaries_kernel<<<nblocks, TPB>>>((const int4*)batch, batch, n);
    }

    // phase B: one warp per segment, sum + MLP fused
    {
        int nblocks = BN / (TPB / 32);   // 2048, covers BN exactly
        segmean_mlp_kernel<<<nblocks, TPB>>>((const float4*)x, u, W1, b1, W2, b2, out);
    }
}

// round 9
// speedup vs baseline: 1.5541x; 1.2297x over previous
#include <cuda_runtime.h>

#define BN  16384   // number of segments
#define TPB 256     // phase A block size
#define IT  8       // int4-chunks per lane per warp tile (phase A)

#define TPB_B 128   // phase B block size (4 warps/block, 4096 blocks)

// Segment start offsets. g_start[s] = first node index of segment s; g_start[BN] = n.
// Fully rewritten on every launch (no reset pass needed). No cudaMalloc.
__device__ int g_start[BN + 1];

__device__ __forceinline__ void fill_range(int u, int v, int i) {
    // batch is sorted: for every s in (u, v], segment s starts at node i.
    int s  = (u + 1 > 0)  ? u + 1 : 0;
    int se = (v < BN)     ? v     : BN;
    for (; s <= se; ++s) g_start[s] = i;
}

// ---------------- phase A: boundary detection over batch (20 MB) ----------------
__global__ void __launch_bounds__(TPB) boundaries_kernel(
    const int4* __restrict__ bat4,
    const int*  __restrict__ batch,
    int n)
{
    const int lane = threadIdx.x & 31;
    const int warp = blockIdx.x * (TPB / 32) + (threadIdx.x >> 5);
    const int nchunks = n >> 2;           // full int4 chunks
    const int c0 = warp * (32 * IT);

    if (c0 < nchunks) {
        int carry = (c0 == 0) ? -1 : batch[c0 * 4 - 1];  // element before this warp tile
        #pragma unroll
        for (int it = 0; it < IT; ++it) {
            int  c   = c0 + it * 32 + lane;
            bool act = (c < nchunks);
            int4 b   = make_int4(0, 0, 0, 0);
            if (act) b = bat4[c];

            int pl   = __shfl_up_sync(0xffffffffu, b.w, 1);
            int prev = (lane == 0) ? carry : pl;

            if (act) {
                if ((prev ^ b.x) | (b.x ^ b.y) | (b.y ^ b.z) | (b.z ^ b.w)) {
                    int i = c * 4;
                    fill_range(prev, b.x, i);
                    fill_range(b.x,  b.y, i + 1);
                    fill_range(b.y,  b.z, i + 2);
                    fill_range(b.z,  b.w, i + 3);
                }
            }
            carry = __shfl_sync(0xffffffffu, b.w, 31);
        }
    }

    // One thread handles the scalar tail (< 4 elems) and the end sentinel.
    if (blockIdx.x == 0 && threadIdx.x == 0) {
        int i0   = nchunks * 4;
        int prev = (i0 == 0) ? -1 : batch[i0 - 1];
        for (int i = i0; i < n; ++i) {
            int b = batch[i];
            fill_range(prev, b, i);
            prev = b;
        }
        fill_range(prev, BN, n);   // g_start[s]=n beyond the last segment, incl. sentinel
    }
}

// -------- phase B: per-segment contiguous sum + fused MLP (reads x, 80 MB) --------
// launch_bounds(128, 16): force regs <= 32 -> 16 blocks/SM -> 64 warps (100% occ).
__global__ void __launch_bounds__(TPB_B, 16) segmean_mlp_kernel(
    const float4* __restrict__ x,
    const float*  __restrict__ u,
    const float*  __restrict__ W1,  // [5,5] row-major
    const float*  __restrict__ b1,  // [5]
    const float*  __restrict__ W2,  // [5,1]
    const float*  __restrict__ b2,  // [1]
    float* __restrict__ out)
{
    const int seg  = blockIdx.x * (TPB_B / 32) + (threadIdx.x >> 5);  // grid covers BN exactly
    const int lane = threadIdx.x & 31;

    const int s = g_start[seg];
    const int e = g_start[seg + 1];

    float4 a0 = make_float4(0.f, 0.f, 0.f, 0.f);
    float4 a1 = make_float4(0.f, 0.f, 0.f, 0.f);

    // plain unroll-2 streaming (R6 structure), pointer-increment addressing
    const float4* p = x + s + lane;
    int rem = e - (s + lane);            // elements this lane still owns (strided by 32)
    for (; rem > 32; rem -= 64, p += 64) {
        float4 v0 = __ldcs(p);
        float4 v1 = __ldcs(p + 32);
        a0.x += v0.x; a0.y += v0.y; a0.z += v0.z; a0.w += v0.w;
        a1.x += v1.x; a1.y += v1.y; a1.z += v1.z; a1.w += v1.w;
    }
    if (rem > 0) {
        float4 v0 = __ldcs(p);
        a0.x += v0.x; a0.y += v0.y; a0.z += v0.z; a0.w += v0.w;
    }
    a0.x += a1.x; a0.y += a1.y; a0.z += a1.z; a0.w += a1.w;

    // warp reduction (deterministic tree; 4 independent chains overlap)
    #pragma unroll
    for (int o = 16; o > 0; o >>= 1) {
        a0.x += __shfl_down_sync(0xffffffffu, a0.x, o);
        a0.y += __shfl_down_sync(0xffffffffu, a0.y, o);
        a0.z += __shfl_down_sync(0xffffffffu, a0.z, o);
        a0.w += __shfl_down_sync(0xffffffffu, a0.w, o);
    }

    if (lane == 0) {
        float cnt = (float)(e - s);
        float inv = (cnt > 0.f) ? (1.f / cnt) : 0.f;

        float h[5];
        h[0] = __ldg(&u[seg]);
        h[1] = a0.x * inv; h[2] = a0.y * inv;
        h[3] = a0.z * inv; h[4] = a0.w * inv;

        float o = __ldg(&b2[0]);
        #pragma unroll
        for (int j = 0; j < 5; ++j) {
            float t = __ldg(&b1[j]);
            #pragma unroll
            for (int k = 0; k < 5; ++k) t += h[k] * __ldg(&W1[k * 5 + j]);
            t = (t > 0.f) ? t : 0.1f * t;
            o += t * __ldg(&W2[j]);
        }
        out[seg] = o;
    }
}

extern "C" void kernel_launch(void* const* d_in, const int* in_sizes, int n_in,
                              void* d_out, int out_size) {
    const float* x     = (const float*)d_in[0];
    const int*   batch = (const int*)d_in[1];
    const float* u     = (const float*)d_in[2];
    const float* W1    = (const float*)d_in[3];
    const float* b1    = (const float*)d_in[4];
    const float* W2    = (const float*)d_in[5];
    const float* b2    = (const float*)d_in[6];
    float* out = (float*)d_out;

    int n = in_sizes[1];  // number of nodes

    // phase A: boundary detection
    {
        int nchunks = n >> 2;
        long long nwarps = ((long long)nchunks + (32 * IT) - 1) / (32 * IT);
        int nblocks = (int)((nwarps + (TPB / 32) - 1) / (TPB / 32));
        if (nblocks < 1) nblocks = 1;
        boundaries_kernel<<<nblocks, TPB>>>((const int4*)batch, batch, n);
    }

    // phase B: one warp per segment, sum + MLP fused
    {
        int nblocks = BN / (TPB_B / 32);   // 4096, covers BN exactly
        segmean_mlp_kernel<<<nblocks, TPB_B>>>((const float4*)x, u, W1, b1, W2, b2, out);
    }
}